// round 16
// baseline (speedup 1.0000x reference)
#include <cuda_runtime.h>
#include <math.h>

#define BB 8
#define NP 2048
#define EP 32768
#define NT (BB*NP)      // 16384 total nodes
#define ET (BB*EP)      // 262144 total edges
#define HH 128
#define NL 3
#define ES 50

// ---- edge-kernel tiling ----
#define MT 64
#define NTILES (ET/MT)          // 4096
#define GRID_EDGE 444           // 3 blocks/SM

// gate table
#define TABN 4096
#define TABH 0.00125f
#define TABINV 800.0f

// edge-kernel smem (words of bf16x2), stride 68 (≡4 mod 32, conflict-free)
#define OFFE_A1 0
#define OFFE_W2 (OFFE_A1 + MT*68)       // 4352
#define SMEM_EDGE (OFFE_W2 + HH*68)     // 13056 words = 52224 B

// table-kernel smem
#define GS 36
#define GH 68
#define OFFG_ES 0
#define OFFG_W1 (OFFG_ES + 128*GS)
#define OFFG_H  (OFFG_W1 + 128*GS)
#define OFFG_W2 (OFFG_H + 128*GH)
#define SMEM_GATE (OFFG_W2 + 128*GH)    // 26624 words

// node-kernel smem layouts (stride 68)
#define NS 68
#define OFFP_A 0
#define OFFP_W (OFFP_A + 64*NS)         // 4352
#define SMEM_PRE (OFFP_W + 128*NS)      // 13056 words (split-N)
#define OFFU_A 0
#define OFFU_H (OFFU_A + 64*NS)
#define OFFU_W1 (OFFU_H + 64*NS)
#define OFFU_W2 (OFFU_W1 + HH*NS)
#define SMEM_UPD (OFFU_W2 + HH*NS)      // 26112 words

// transposed bf16 weight scratch offsets (words)
#define GWT_PRE(l) ((l)*16384)
#define GWT_S1(l)  (49152 + (l)*8192)
#define GWT_S2(l)  (73728 + (l)*8192)
#define GWT_N2(l)  (98304 + (l)*8192)
#define GWT_E1(l)  (122880 + (l)*4096)
#define GWT_E2(l)  (135168 + (l)*8192)
#define GWT_TOTAL  159744

// ---- scratch (no allocations allowed; __device__ globals) ----
__device__ float g_state[NT*HH];
__device__ float g_S[NT*HH];
__device__ float g_R[NT*HH];
__device__ float g_msum[NT*HH];
__device__ int   g_off[BB];
__device__ __align__(16) unsigned g_wt[GWT_TOTAL];
__device__ __align__(16) float g_tab[NL*TABN*HH];   // fp32 gate table, 6MB (L2-resident)

__device__ __forceinline__ float sspf(float x){
    return fmaxf(x, 0.0f) + __logf(1.0f + __expf(-fabsf(x))) - 0.69314718055994530942f;
}
__device__ __forceinline__ unsigned bf2(float lo, float hi){
    unsigned r; asm("cvt.rn.bf16x2.f32 %0, %1, %2;" : "=r"(r) : "f"(hi), "f"(lo)); return r;
}
__device__ __forceinline__ void mma16(float* d, unsigned a0, unsigned a1, unsigned a2,
                                      unsigned a3, unsigned b0, unsigned b1){
    asm volatile("mma.sync.aligned.m16n8k16.row.col.f32.bf16.bf16.f32 "
        "{%0,%1,%2,%3},{%4,%5,%6,%7},{%8,%9},{%0,%1,%2,%3};"
        : "+f"(d[0]),"+f"(d[1]),"+f"(d[2]),"+f"(d[3])
        : "r"(a0),"r"(a1),"r"(a2),"r"(a3),"r"(b0),"r"(b1));
}
__device__ __forceinline__ void ldsm4(unsigned addr, unsigned& d0, unsigned& d1,
                                      unsigned& d2, unsigned& d3){
    asm volatile("ldmatrix.sync.aligned.m8n8.x4.shared.b16 {%0,%1,%2,%3}, [%4];"
        : "=r"(d0),"=r"(d1),"=r"(d2),"=r"(d3) : "r"(addr));
}
__device__ __forceinline__ void red2(float* p, float x, float y){
    asm volatile("red.global.add.v2.f32 [%0], {%1, %2};"
        :: "l"(p), "f"(x), "f"(y) : "memory");
}
__device__ __forceinline__ float gsf(float d, int j){
    if (j >= ES) return 0.0f;
    float dd = d - 0.1f*(float)j;
    return __expf(-dd*dd*50.0f);
}

// ---------------------------------------------------------------------------
__global__ void k_init(const int* __restrict__ nodes, const float* __restrict__ emb,
                       const int* __restrict__ num_nodes){
    int i = blockIdx.x*blockDim.x + threadIdx.x;
    if (i == 0){
        int acc = 0;
        for (int b = 0; b < BB; b++){ g_off[b] = acc; acc += num_nodes[b]; }
    }
    if (i < NT*HH){
        int node = i >> 7, c = i & 127;
        g_state[i] = emb[nodes[node]*HH + c];
    }
}

// ---------------------------------------------------------------------------
// one-shot: transpose+convert ALL weights (all layers) into g_wt (bf16x2)
// ---------------------------------------------------------------------------
__global__ void k_wt(const float* __restrict__ Wn1, const float* __restrict__ Ws1,
                     const float* __restrict__ Ws2, const float* __restrict__ Wn2,
                     const float* __restrict__ We1, const float* __restrict__ We2){
    int i = blockIdx.x*blockDim.x + threadIdx.x;
    if (i >= 3*53248) return;
    int l = i / 53248, r = i - l*53248;
    if (r < 16384){
        int c = r >> 6, kw = r & 63;
        int half = c >> 7, n = c & 127;
        const float* W = Wn1 + l*2*HH*HH + half*HH*HH;
        g_wt[GWT_PRE(l) + r] = bf2(W[(2*kw)*HH + n], W[(2*kw+1)*HH + n]);
    } else if (r < 24576){
        int q = r - 16384; int n = q >> 6, kw = q & 63;
        const float* W = Ws1 + l*HH*HH;
        g_wt[GWT_S1(l) + q] = bf2(W[(2*kw)*HH + n], W[(2*kw+1)*HH + n]);
    } else if (r < 32768){
        int q = r - 24576; int n = q >> 6, kw = q & 63;
        const float* W = Ws2 + l*HH*HH;
        g_wt[GWT_S2(l) + q] = bf2(W[(2*kw)*HH + n], W[(2*kw+1)*HH + n]);
    } else if (r < 40960){
        int q = r - 32768; int n = q >> 6, kw = q & 63;
        const float* W = Wn2 + l*HH*HH;
        g_wt[GWT_N2(l) + q] = bf2(W[(2*kw)*HH + n], W[(2*kw+1)*HH + n]);
    } else if (r < 45056){
        int q = r - 40960; int n = q >> 5, kw = q & 31;
        const float* W = We1 + l*ES*HH;
        float lo = (2*kw   < ES) ? W[(2*kw  )*HH + n] : 0.0f;
        float hi = (2*kw+1 < ES) ? W[(2*kw+1)*HH + n] : 0.0f;
        g_wt[GWT_E1(l) + q] = bf2(lo, hi);
    } else {
        int q = r - 45056; int n = q >> 6, kw = q & 63;
        const float* W = We2 + l*HH*HH;
        g_wt[GWT_E2(l) + q] = bf2(W[(2*kw)*HH + n], W[(2*kw+1)*HH + n]);
    }
}

// ---------------------------------------------------------------------------
// gate TABLE build (all layers): row i <-> distance d = i*TABH  (fp32 output)
// ---------------------------------------------------------------------------
__global__ void __launch_bounds__(256, 2) k_tab(
    const float* __restrict__ be1, const float* __restrict__ be2)
{
    extern __shared__ unsigned smw[];
    int t = threadIdx.x, lane = t & 31, w = t >> 5;
    int g = lane >> 2, tid = lane & 3;
    int layer = blockIdx.x >> 5;
    int e0t = (blockIdx.x & 31)*128;
    const float* b1v = be1 + layer*HH;
    const float* b2v = be2 + layer*HH;

    {
        const uint4* s1 = (const uint4*)(g_wt + GWT_E1(layer));
        for (int i = t; i < 1024; i += 256){
            int n = i >> 3, kq = i & 7;
            *(uint4*)&smw[OFFG_W1 + n*GS + kq*4] = s1[i];
        }
        const uint4* s2 = (const uint4*)(g_wt + GWT_E2(layer));
        for (int i = t; i < 2048; i += 256){
            int n = i >> 4, kq = i & 15;
            *(uint4*)&smw[OFFG_W2 + n*GH + kq*4] = s2[i];
        }
    }
    for (int i = t; i < 4096; i += 256){
        int r = i >> 5, kw = i & 31;
        float d = (float)(e0t + r)*TABH;
        smw[OFFG_ES + r*GS + kw] = bf2(gsf(d, 2*kw), gsf(d, 2*kw+1));
    }
    __syncthreads();

    unsigned sb = (unsigned)__cvta_generic_to_shared(smw);
    int rowA = w*16 + (lane & 7) + ((lane >> 3) & 1)*8;
    int kSel = (lane >> 4)*4;
    unsigned aES = sb + (unsigned)(OFFG_ES + rowA*GS + kSel)*4u;
    unsigned aH  = sb + (unsigned)(OFFG_H  + rowA*GH + kSel)*4u;
    int rowB8 = lane & 7;
    int bSel  = (lane >> 3)*4;
    unsigned aW1 = sb + (unsigned)(OFFG_W1 + rowB8*GS + bSel)*4u;
    unsigned aW2 = sb + (unsigned)(OFFG_W2 + rowB8*GH + bSel)*4u;
    const unsigned S1STEP = 8u*GS*4u, S2STEP = 8u*GH*4u;
    int r0 = w*16 + g, r1 = r0 + 8;

    float d[16][4];
#pragma unroll
    for (int n = 0; n < 16; n++)
#pragma unroll
        for (int j = 0; j < 4; j++) d[n][j] = 0.f;

#pragma unroll
    for (int kt2 = 0; kt2 < 2; kt2++){
        unsigned a0,a1,a2,a3, a4,a5,a6,a7;
        ldsm4(aES + kt2*64u,       a0,a1,a2,a3);
        ldsm4(aES + kt2*64u + 32u, a4,a5,a6,a7);
#pragma unroll
        for (int ntl = 0; ntl < 16; ntl++){
            unsigned b0,b1,b2,b3;
            ldsm4(aW1 + ntl*S1STEP + kt2*64u, b0,b1,b2,b3);
            mma16(d[ntl], a0,a1,a2,a3, b0,b1);
            mma16(d[ntl], a4,a5,a6,a7, b2,b3);
        }
    }
#pragma unroll
    for (int ntl = 0; ntl < 16; ntl++){
        int c0 = ntl*8 + 2*tid;
        float b1a = b1v[c0], b1b = b1v[c0+1];
        smw[OFFG_H + r0*GH + (c0>>1)] = bf2(sspf(d[ntl][0]+b1a), sspf(d[ntl][1]+b1b));
        smw[OFFG_H + r1*GH + (c0>>1)] = bf2(sspf(d[ntl][2]+b1a), sspf(d[ntl][3]+b1b));
    }
    __syncthreads();

#pragma unroll
    for (int n = 0; n < 16; n++)
#pragma unroll
        for (int j = 0; j < 4; j++) d[n][j] = 0.f;
#pragma unroll
    for (int kt2 = 0; kt2 < 4; kt2++){
        unsigned a0,a1,a2,a3, a4,a5,a6,a7;
        ldsm4(aH + kt2*64u,       a0,a1,a2,a3);
        ldsm4(aH + kt2*64u + 32u, a4,a5,a6,a7);
#pragma unroll
        for (int ntl = 0; ntl < 16; ntl++){
            unsigned b0,b1,b2,b3;
            ldsm4(aW2 + ntl*S2STEP + kt2*64u, b0,b1,b2,b3);
            mma16(d[ntl], a0,a1,a2,a3, b0,b1);
            mma16(d[ntl], a4,a5,a6,a7, b2,b3);
        }
    }

    float dd0 = (float)(e0t + r0)*TABH, dd1 = (float)(e0t + r1)*TABH;
    float cut0 = 1.0f/(1.0f + __expf(5.0f*(dd0 - 3.5f)));
    float cut1 = 1.0f/(1.0f + __expf(5.0f*(dd1 - 3.5f)));
    float* tp0 = g_tab + ((size_t)layer*TABN + e0t + r0)*HH;
    float* tp1 = g_tab + ((size_t)layer*TABN + e0t + r1)*HH;
#pragma unroll
    for (int ntl = 0; ntl < 16; ntl++){
        int c0 = ntl*8 + 2*tid;
        float q0 = b2v[c0], q1 = b2v[c0+1];
        *(float2*)&tp0[c0] = make_float2((d[ntl][0]+q0)*cut0, (d[ntl][1]+q1)*cut0);
        *(float2*)&tp1[c0] = make_float2((d[ntl][2]+q0)*cut1, (d[ntl][3]+q1)*cut1);
    }
}

// ---------------------------------------------------------------------------
// node pre-GEMM (bf16 mma), SPLIT-N: 512 blocks; nhalf=0 -> S, nhalf=1 -> R
// ---------------------------------------------------------------------------
__global__ void __launch_bounds__(256, 4) k_pre(int layer){
    extern __shared__ unsigned smw[];
    int t = threadIdx.x, lane = t & 31, w = t >> 5;
    int g = lane >> 2, tid = lane & 3;
    int row0  = (blockIdx.x >> 1)*64;
    int nhalf = blockIdx.x & 1;

    {
        float4 z = make_float4(0.f,0.f,0.f,0.f);
        for (int i = t; i < 1024; i += 256){
            int r = i >> 4, c4 = i & 15;
            *(float4*)&g_msum[(row0 + r)*HH + nhalf*64 + c4*4] = z;
        }
    }
    for (int i = t; i < 64*64; i += 256){
        int r = i >> 6, kw = i & 63;
        float2 v = *(const float2*)&g_state[(row0 + r)*HH + 2*kw];
        smw[OFFP_A + r*NS + kw] = bf2(v.x, v.y);
    }
    {
        const uint4* src = (const uint4*)(g_wt + GWT_PRE(layer) + nhalf*128*64);
        for (int i = t; i < 2048; i += 256){
            int n = i >> 4, kq = i & 15;
            *(uint4*)&smw[OFFP_W + n*NS + kq*4] = src[i];
        }
    }
    __syncthreads();

    int wm = w & 3, wn = w >> 2;
    float d[8][4];
#pragma unroll
    for (int n = 0; n < 8; n++)
#pragma unroll
        for (int j = 0; j < 4; j++) d[n][j] = 0.f;

    unsigned sb = (unsigned)__cvta_generic_to_shared(smw);
    int rowA = wm*16 + (lane & 7) + ((lane >> 3) & 1)*8;
    int kSel = (lane >> 4)*4;
    unsigned aA = sb + (unsigned)(OFFP_A + rowA*NS + kSel)*4u;
    int rowBn = wn*64 + (lane & 7);
    int bSel  = (lane >> 3)*4;
    unsigned aW = sb + (unsigned)(OFFP_W + rowBn*NS + bSel)*4u;
    const unsigned NSTEP = 8u*NS*4u;

#pragma unroll
    for (int kt2 = 0; kt2 < 4; kt2++){
        unsigned a0,a1,a2,a3, a4,a5,a6,a7;
        ldsm4(aA + kt2*64u,       a0,a1,a2,a3);
        ldsm4(aA + kt2*64u + 32u, a4,a5,a6,a7);
#pragma unroll
        for (int ntl = 0; ntl < 8; ntl++){
            unsigned b0,b1,b2,b3;
            ldsm4(aW + ntl*NSTEP + kt2*64u, b0,b1,b2,b3);
            mma16(d[ntl], a0,a1,a2,a3, b0,b1);
            mma16(d[ntl], a4,a5,a6,a7, b2,b3);
        }
    }

    float* dst = nhalf ? g_R : g_S;
    int r0 = row0 + wm*16 + g, r1 = r0 + 8;
#pragma unroll
    for (int ntl = 0; ntl < 8; ntl++){
        int c = wn*64 + ntl*8 + 2*tid;
        *(float2*)&dst[r0*HH + c] = make_float2(d[ntl][0], d[ntl][1]);
        *(float2*)&dst[r1*HH + c] = make_float2(d[ntl][2], d[ntl][3]);
    }
}

// ---------------------------------------------------------------------------
// persistent edge kernel, MT=64: per-tile overheads halved per edge
// 8 warps: wm = w&3 (rows wm*16..+15), wn = w>>2 (cols wn*64..+63, 8 ntl)
// ---------------------------------------------------------------------------
__global__ void __launch_bounds__(256, 3) k_edge(
    const int* __restrict__ atom_edges, const float* __restrict__ feats,
    const float* __restrict__ bn1, const float* __restrict__ bn2, int layer)
{
    extern __shared__ unsigned smw[];
    int t = threadIdx.x, lane = t & 31, w = t >> 5;
    int g = lane >> 2, tid = lane & 3;

    {
        const uint4* src = (const uint4*)(g_wt + GWT_N2(layer));
        for (int i = t; i < 2048; i += 256){
            int n = i >> 4, kq = i & 15;
            *(uint4*)&smw[OFFE_W2 + n*68 + kq*4] = src[i];
        }
    }

    int wm = w & 3, wn = w >> 2;
    int r0 = wm*16 + g, r1 = r0 + 8;
    int fc4 = (t & 31)*4;      // fill column quad
    int fr8 = t >> 5;          // fill row base (0..7); rows fr8 + 8j, j=0..7
    float4 b4 = *(const float4*)&bn1[fc4];
    float bn2h[8][2];
#pragma unroll
    for (int ntl = 0; ntl < 8; ntl++){
        int c0 = wn*64 + ntl*8 + 2*tid;
        bn2h[ntl][0] = bn2[c0]; bn2h[ntl][1] = bn2[c0+1];
    }

    unsigned sb = (unsigned)__cvta_generic_to_shared(smw);
    int rowA = wm*16 + (lane & 7) + ((lane >> 3) & 1)*8;
    int kSel = (lane >> 4)*4;
    unsigned aA1 = sb + (unsigned)(OFFE_A1 + rowA*68 + kSel)*4u;
    int rowBn = wn*64 + (lane & 7);
    int bSel  = (lane >> 3)*4;
    unsigned aW2 = sb + (unsigned)(OFFE_W2 + rowBn*68 + bSel)*4u;
    const unsigned NSTEP = 8u*68*4u;
    const float* T = g_tab + (size_t)layer*TABN*HH;

    for (int tile = blockIdx.x; tile < NTILES; tile += gridDim.x){
        int e0t = tile*MT;
        int off = g_off[tile >> 9];   // 512 tiles per graph (EP/MT)

        // chunk 0 gathers issued before barrier (reg targets; no hazard)
        float4 sv[4], rv[4];
#pragma unroll
        for (int j = 0; j < 4; j++){
            int e  = e0t + fr8 + 8*j;
            int sn = atom_edges[2*e]   + off;
            int rc = atom_edges[2*e+1] + off;
            sv[j] = *(const float4*)&g_S[sn*HH + fc4];
            rv[j] = *(const float4*)&g_R[rc*HH + fc4];
        }
        __syncthreads();   // prev tile's A1 reads complete

#pragma unroll
        for (int j = 0; j < 4; j++){
            int m = fr8 + 8*j;
            unsigned w0 = bf2(sspf(sv[j].x + rv[j].x + b4.x), sspf(sv[j].y + rv[j].y + b4.y));
            unsigned w1 = bf2(sspf(sv[j].z + rv[j].z + b4.z), sspf(sv[j].w + rv[j].w + b4.w));
            *(uint2*)&smw[OFFE_A1 + m*68 + (fc4 >> 1)] = make_uint2(w0, w1);
        }
        // chunk 1
#pragma unroll
        for (int j = 0; j < 4; j++){
            int e  = e0t + fr8 + 8*(4+j);
            int sn = atom_edges[2*e]   + off;
            int rc = atom_edges[2*e+1] + off;
            sv[j] = *(const float4*)&g_S[sn*HH + fc4];
            rv[j] = *(const float4*)&g_R[rc*HH + fc4];
        }
#pragma unroll
        for (int j = 0; j < 4; j++){
            int m = fr8 + 8*(4+j);
            unsigned w0 = bf2(sspf(sv[j].x + rv[j].x + b4.x), sspf(sv[j].y + rv[j].y + b4.y));
            unsigned w1 = bf2(sspf(sv[j].z + rv[j].z + b4.z), sspf(sv[j].w + rv[j].w + b4.w));
            *(uint2*)&smw[OFFE_A1 + m*68 + (fc4 >> 1)] = make_uint2(w0, w1);
        }

        // per-warp edge distances -> table coords (cheap; before barrier)
        float u0 = feats[e0t + r0]*TABINV;
        float u1 = feats[e0t + r1]*TABINV;
        int i0 = (int)u0, i1 = (int)u1;
        float f0 = u0 - (float)i0, f1 = u1 - (float)i1;
        const float* pa = T + (size_t)i0*HH;
        const float* pb = T + (size_t)i1*HH;
        __syncthreads();   // A1 complete

        // GEMM: mn = A1 @ Wn2^T  (M=64 tile; B frags reused over 4 M-groups)
        float dm[8][4];
#pragma unroll
        for (int i = 0; i < 8; i++)
#pragma unroll
            for (int j = 0; j < 4; j++) dm[i][j] = 0.0f;
#pragma unroll
        for (int kt2 = 0; kt2 < 4; kt2++){
            unsigned a0,a1,a2,a3, a4,a5,a6,a7;
            ldsm4(aA1 + kt2*64u,       a0,a1,a2,a3);
            ldsm4(aA1 + kt2*64u + 32u, a4,a5,a6,a7);
#pragma unroll
            for (int ntl = 0; ntl < 8; ntl++){
                unsigned b0,b1,b2,b3;
                ldsm4(aW2 + ntl*NSTEP + kt2*64u, b0,b1,b2,b3);
                mma16(dm[ntl], a0,a1,a2,a3, b0,b1);
                mma16(dm[ntl], a4,a5,a6,a7, b2,b3);
            }
        }

        // gate lerp + combine + red2 scatter, in 4 batches of 2 ntl (reg-lean)
        int rcv0 = atom_edges[2*(e0t + r0) + 1] + off;
        int rcv1 = atom_edges[2*(e0t + r1) + 1] + off;
#pragma unroll
        for (int nb = 0; nb < 4; nb++){
            float2 ga0[2], ga1[2], gb0[2], gb1[2];
#pragma unroll
            for (int k = 0; k < 2; k++){
                int c0 = wn*64 + (2*nb + k)*8 + 2*tid;
                ga0[k] = *(const float2*)&pa[c0];
                ga1[k] = *(const float2*)&pa[HH + c0];
                gb0[k] = *(const float2*)&pb[c0];
                gb1[k] = *(const float2*)&pb[HH + c0];
            }
#pragma unroll
            for (int k = 0; k < 2; k++){
                int ntl = 2*nb + k;
                int c0 = wn*64 + ntl*8 + 2*tid;
                float g0x = ga0[k].x + (ga1[k].x - ga0[k].x)*f0;
                float g0y = ga0[k].y + (ga1[k].y - ga0[k].y)*f0;
                float g1x = gb0[k].x + (gb1[k].x - gb0[k].x)*f1;
                float g1y = gb0[k].y + (gb1[k].y - gb0[k].y)*f1;
                red2(&g_msum[rcv0*HH + c0], (dm[ntl][0]+bn2h[ntl][0])*g0x,
                                            (dm[ntl][1]+bn2h[ntl][1])*g0y);
                red2(&g_msum[rcv1*HH + c0], (dm[ntl][2]+bn2h[ntl][0])*g1x,
                                            (dm[ntl][3]+bn2h[ntl][1])*g1y);
            }
        }
    }
}

// ---------------------------------------------------------------------------
// node update (bf16 mma): state += ssp(msum @ Ws1 + bs1) @ Ws2 + bs2
// ---------------------------------------------------------------------------
__global__ void __launch_bounds__(256, 2) k_upd(int layer,
                      const float* __restrict__ bs1, const float* __restrict__ bs2,
                      float* __restrict__ out)
{
    extern __shared__ unsigned smw[];
    int t = threadIdx.x, lane = t & 31, w = t >> 5;
    int g = lane >> 2, tid = lane & 3;
    int row0 = blockIdx.x*64;

    for (int i = t; i < 64*64; i += 256){
        int r = i >> 6, kw = i & 63;
        float2 v = *(const float2*)&g_msum[(row0 + r)*HH + 2*kw];
        smw[OFFU_A + r*NS + kw] = bf2(v.x, v.y);
    }
    {
        const uint4* s1 = (const uint4*)(g_wt + GWT_S1(layer));
        const uint4* s2 = (const uint4*)(g_wt + GWT_S2(layer));
        for (int i = t; i < 2048; i += 256){
            int n = i >> 4, kq = i & 15;
            *(uint4*)&smw[OFFU_W1 + n*NS + kq*4] = s1[i];
            *(uint4*)&smw[OFFU_W2 + n*NS + kq*4] = s2[i];
        }
    }
    __syncthreads();

    int wm = w & 3, wn = w >> 2;
    unsigned sb = (unsigned)__cvta_generic_to_shared(smw);
    int rowA = wm*16 + (lane & 7) + ((lane >> 3) & 1)*8;
    int kSel = (lane >> 4)*4;
    unsigned aA  = sb + (unsigned)(OFFU_A + rowA*NS + kSel)*4u;
    unsigned aH  = sb + (unsigned)(OFFU_H + rowA*NS + kSel)*4u;
    int rowBn = wn*64 + (lane & 7);
    int bSel  = (lane >> 3)*4;
    unsigned aW1 = sb + (unsigned)(OFFU_W1 + rowBn*NS + bSel)*4u;
    unsigned aW2 = sb + (unsigned)(OFFU_W2 + rowBn*NS + bSel)*4u;
    const unsigned NSTEP = 8u*NS*4u;

    float d[8][4];
#pragma unroll
    for (int n = 0; n < 8; n++)
#pragma unroll
        for (int j = 0; j < 4; j++) d[n][j] = 0.f;
#pragma unroll
    for (int kt2 = 0; kt2 < 4; kt2++){
        unsigned a0,a1,a2,a3, a4,a5,a6,a7;
        ldsm4(aA + kt2*64u,       a0,a1,a2,a3);
        ldsm4(aA + kt2*64u + 32u, a4,a5,a6,a7);
#pragma unroll
        for (int ntl = 0; ntl < 8; ntl++){
            unsigned b0,b1,b2,b3;
            ldsm4(aW1 + ntl*NSTEP + kt2*64u, b0,b1,b2,b3);
            mma16(d[ntl], a0,a1,a2,a3, b0,b1);
            mma16(d[ntl], a4,a5,a6,a7, b2,b3);
        }
    }
    {
        int r0 = wm*16 + g, r1 = r0 + 8;
#pragma unroll
        for (int ntl = 0; ntl < 8; ntl++){
            int c0 = wn*64 + ntl*8 + 2*tid;
            float b1a = bs1[c0], b1b = bs1[c0+1];
            int cw = c0 >> 1;
            smw[OFFU_H + r0*NS + cw] = bf2(sspf(d[ntl][0]+b1a), sspf(d[ntl][1]+b1b));
            smw[OFFU_H + r1*NS + cw] = bf2(sspf(d[ntl][2]+b1a), sspf(d[ntl][3]+b1b));
        }
    }
    __syncthreads();

    float e2[8][4];
#pragma unroll
    for (int n = 0; n < 8; n++)
#pragma unroll
        for (int j = 0; j < 4; j++) e2[n][j] = 0.f;
#pragma unroll
    for (int kt2 = 0; kt2 < 4; kt2++){
        unsigned a0,a1,a2,a3, a4,a5,a6,a7;
        ldsm4(aH + kt2*64u,       a0,a1,a2,a3);
        ldsm4(aH + kt2*64u + 32u, a4,a5,a6,a7);
#pragma unroll
        for (int ntl = 0; ntl < 8; ntl++){
            unsigned b0,b1,b2,b3;
            ldsm4(aW2 + ntl*NSTEP + kt2*64u, b0,b1,b2,b3);
            mma16(e2[ntl], a0,a1,a2,a3, b0,b1);
            mma16(e2[ntl], a4,a5,a6,a7, b2,b3);
        }
    }
    {
        int r0 = row0 + wm*16 + g, r1 = r0 + 8;
#pragma unroll
        for (int ntl = 0; ntl < 8; ntl++){
            int c0 = wn*64 + ntl*8 + 2*tid;
            float b2a = bs2[c0], b2b = bs2[c0+1];
            float2 s0 = *(const float2*)&g_state[r0*HH + c0];
            float2 s1 = *(const float2*)&g_state[r1*HH + c0];
            float2 v0 = make_float2(s0.x + e2[ntl][0] + b2a, s0.y + e2[ntl][1] + b2b);
            float2 v1 = make_float2(s1.x + e2[ntl][2] + b2a, s1.y + e2[ntl][3] + b2b);
            *(float2*)&g_state[r0*HH + c0] = v0;
            *(float2*)&g_state[r1*HH + c0] = v1;
            *(float2*)&out[r0*HH + c0] = v0;
            *(float2*)&out[r1*HH + c0] = v1;
        }
    }
}

// ---------------------------------------------------------------------------
extern "C" void kernel_launch(void* const* d_in, const int* in_sizes, int n_in,
                              void* d_out, int out_size)
{
    const int*   nodes      = (const int*)  d_in[0];
    const int*   atom_edges = (const int*)  d_in[1];
    const float* feats      = (const float*)d_in[2];
    const int*   num_nodes  = (const int*)  d_in[3];
    // d_in[4] = num_atom_edges (all == EP, unused)
    const float* emb = (const float*)d_in[5];
    const float* Wn1 = (const float*)d_in[6];
    const float* bn1 = (const float*)d_in[7];
    const float* Wn2 = (const float*)d_in[8];
    const float* bn2 = (const float*)d_in[9];
    const float* We1 = (const float*)d_in[10];
    const float* be1 = (const float*)d_in[11];
    const float* We2 = (const float*)d_in[12];
    const float* be2 = (const float*)d_in[13];
    const float* Ws1 = (const float*)d_in[14];
    const float* bs1 = (const float*)d_in[15];
    const float* Ws2 = (const float*)d_in[16];
    const float* bs2 = (const float*)d_in[17];
    float* out = (float*)d_out;

    cudaFuncSetAttribute(k_edge, cudaFuncAttributeMaxDynamicSharedMemorySize,
                         SMEM_EDGE*sizeof(unsigned));
    cudaFuncSetAttribute(k_tab, cudaFuncAttributeMaxDynamicSharedMemorySize,
                         SMEM_GATE*sizeof(unsigned));
    cudaFuncSetAttribute(k_pre, cudaFuncAttributeMaxDynamicSharedMemorySize,
                         SMEM_PRE*sizeof(unsigned));
    cudaFuncSetAttribute(k_upd, cudaFuncAttributeMaxDynamicSharedMemorySize,
                         SMEM_UPD*sizeof(unsigned));

    k_init<<<(NT*HH + 255)/256, 256>>>(nodes, emb, num_nodes);
    k_wt<<<624, 256>>>(Wn1, Ws1, Ws2, Wn2, We1, We2);
    k_tab<<<NL*32, 256, SMEM_GATE*sizeof(unsigned)>>>(be1, be2);
    for (int l = 0; l < NL; l++){
        k_pre<<<NT/32, 256, SMEM_PRE*sizeof(unsigned)>>>(l);
        k_edge<<<GRID_EDGE, 256, SMEM_EDGE*sizeof(unsigned)>>>(atom_edges, feats,
            bn1 + l*HH, bn2 + l*HH, l);
        k_upd<<<NT/64, 256, SMEM_UPD*sizeof(unsigned)>>>(l, bs1 + l*HH, bs2 + l*HH,
                              out + (size_t)l*NT*HH);
    }
}

// round 17
// speedup vs baseline: 1.0923x; 1.0923x over previous
#include <cuda_runtime.h>
#include <math.h>

#define BB 8
#define NP 2048
#define EP 32768
#define NT (BB*NP)      // 16384 total nodes
#define ET (BB*EP)      // 262144 total edges
#define HH 128
#define NL 3
#define ES 50

// ---- edge-kernel tiling ----
#define MT 32
#define NTILES (ET/MT)          // 8192
#define GRID_EDGE 444           // 3 blocks/SM

// gate table
#define TABN 4096
#define TABH 0.00125f
#define TABINV 800.0f

// slim edge-kernel smem (words of bf16x2), stride 68 (≡4 mod 32, conflict-free)
#define OFFE_A1 0
#define OFFE_W2 (OFFE_A1 + MT*68)       // 2176
#define SMEM_EDGE (OFFE_W2 + HH*68)     // 10880 words = 43520 B

// table-kernel smem
#define GS 36
#define GH 68
#define OFFG_ES 0
#define OFFG_W1 (OFFG_ES + 128*GS)
#define OFFG_H  (OFFG_W1 + 128*GS)
#define OFFG_W2 (OFFG_H + 128*GH)
#define SMEM_GATE (OFFG_W2 + 128*GH)    // 26624 words

// node-kernel smem layouts (stride 68)
#define NS 68
#define OFFP_A 0
#define OFFP_W (OFFP_A + 64*NS)         // 4352
#define SMEM_PRE (OFFP_W + 128*NS)      // 13056 words (split-N)
#define OFFU_A 0
#define OFFU_H (OFFU_A + 64*NS)
#define OFFU_W1 (OFFU_H + 64*NS)
#define OFFU_W2 (OFFU_W1 + HH*NS)
#define SMEM_UPD (OFFU_W2 + HH*NS)      // 26112 words

// transposed bf16 weight scratch offsets (words)
#define GWT_PRE(l) ((l)*16384)
#define GWT_S1(l)  (49152 + (l)*8192)
#define GWT_S2(l)  (73728 + (l)*8192)
#define GWT_N2(l)  (98304 + (l)*8192)
#define GWT_E1(l)  (122880 + (l)*4096)
#define GWT_E2(l)  (135168 + (l)*8192)
#define GWT_TOTAL  159744

// ---- scratch (no allocations allowed; __device__ globals) ----
__device__ float g_state[NT*HH];
__device__ float g_S[NT*HH];
__device__ float g_R[NT*HH];
__device__ float g_msum[NT*HH];
__device__ int   g_off[BB];
__device__ __align__(16) unsigned g_wt[GWT_TOTAL];
__device__ __align__(16) float g_tab[NL*TABN*HH];   // fp32 gate table, 6MB (L2-resident)

__device__ __forceinline__ float sspf(float x){
    return fmaxf(x, 0.0f) + __logf(1.0f + __expf(-fabsf(x))) - 0.69314718055994530942f;
}
__device__ __forceinline__ unsigned bf2(float lo, float hi){
    unsigned r; asm("cvt.rn.bf16x2.f32 %0, %1, %2;" : "=r"(r) : "f"(hi), "f"(lo)); return r;
}
__device__ __forceinline__ void mma16(float* d, unsigned a0, unsigned a1, unsigned a2,
                                      unsigned a3, unsigned b0, unsigned b1){
    asm volatile("mma.sync.aligned.m16n8k16.row.col.f32.bf16.bf16.f32 "
        "{%0,%1,%2,%3},{%4,%5,%6,%7},{%8,%9},{%0,%1,%2,%3};"
        : "+f"(d[0]),"+f"(d[1]),"+f"(d[2]),"+f"(d[3])
        : "r"(a0),"r"(a1),"r"(a2),"r"(a3),"r"(b0),"r"(b1));
}
__device__ __forceinline__ void ldsm4(unsigned addr, unsigned& d0, unsigned& d1,
                                      unsigned& d2, unsigned& d3){
    asm volatile("ldmatrix.sync.aligned.m8n8.x4.shared.b16 {%0,%1,%2,%3}, [%4];"
        : "=r"(d0),"=r"(d1),"=r"(d2),"=r"(d3) : "r"(addr));
}
__device__ __forceinline__ void red2(float* p, float x, float y){
    asm volatile("red.global.add.v2.f32 [%0], {%1, %2};"
        :: "l"(p), "f"(x), "f"(y) : "memory");
}
__device__ __forceinline__ float gsf(float d, int j){
    if (j >= ES) return 0.0f;
    float dd = d - 0.1f*(float)j;
    return __expf(-dd*dd*50.0f);
}

// ---------------------------------------------------------------------------
// merged one-shot setup: node embedding gather + offsets (blocks < 8192),
// weight transpose/convert (blocks >= 8192)
// ---------------------------------------------------------------------------
__global__ void k_setup(const int* __restrict__ nodes, const float* __restrict__ emb,
                        const int* __restrict__ num_nodes,
                        const float* __restrict__ Wn1, const float* __restrict__ Ws1,
                        const float* __restrict__ Ws2, const float* __restrict__ Wn2,
                        const float* __restrict__ We1, const float* __restrict__ We2){
    int b = blockIdx.x;
    if (b < 8192){
        int i = b*256 + threadIdx.x;
        if (i == 0){
            int acc = 0;
            for (int q = 0; q < BB; q++){ g_off[q] = acc; acc += num_nodes[q]; }
        }
        if (i < NT*HH){
            int node = i >> 7, c = i & 127;
            g_state[i] = emb[nodes[node]*HH + c];
        }
        return;
    }
    int i = (b - 8192)*256 + threadIdx.x;
    if (i >= 3*53248) return;
    int l = i / 53248, r = i - l*53248;
    if (r < 16384){
        int c = r >> 6, kw = r & 63;
        int half = c >> 7, n = c & 127;
        const float* W = Wn1 + l*2*HH*HH + half*HH*HH;
        g_wt[GWT_PRE(l) + r] = bf2(W[(2*kw)*HH + n], W[(2*kw+1)*HH + n]);
    } else if (r < 24576){
        int q = r - 16384; int n = q >> 6, kw = q & 63;
        const float* W = Ws1 + l*HH*HH;
        g_wt[GWT_S1(l) + q] = bf2(W[(2*kw)*HH + n], W[(2*kw+1)*HH + n]);
    } else if (r < 32768){
        int q = r - 24576; int n = q >> 6, kw = q & 63;
        const float* W = Ws2 + l*HH*HH;
        g_wt[GWT_S2(l) + q] = bf2(W[(2*kw)*HH + n], W[(2*kw+1)*HH + n]);
    } else if (r < 40960){
        int q = r - 32768; int n = q >> 6, kw = q & 63;
        const float* W = Wn2 + l*HH*HH;
        g_wt[GWT_N2(l) + q] = bf2(W[(2*kw)*HH + n], W[(2*kw+1)*HH + n]);
    } else if (r < 45056){
        int q = r - 40960; int n = q >> 5, kw = q & 31;
        const float* W = We1 + l*ES*HH;
        float lo = (2*kw   < ES) ? W[(2*kw  )*HH + n] : 0.0f;
        float hi = (2*kw+1 < ES) ? W[(2*kw+1)*HH + n] : 0.0f;
        g_wt[GWT_E1(l) + q] = bf2(lo, hi);
    } else {
        int q = r - 45056; int n = q >> 6, kw = q & 63;
        const float* W = We2 + l*HH*HH;
        g_wt[GWT_E2(l) + q] = bf2(W[(2*kw)*HH + n], W[(2*kw+1)*HH + n]);
    }
}

// ---------------------------------------------------------------------------
// gate TABLE build (all layers): row i <-> distance d = i*TABH  (fp32 output)
// ---------------------------------------------------------------------------
__global__ void __launch_bounds__(256, 2) k_tab(
    const float* __restrict__ be1, const float* __restrict__ be2)
{
    extern __shared__ unsigned smw[];
    int t = threadIdx.x, lane = t & 31, w = t >> 5;
    int g = lane >> 2, tid = lane & 3;
    int layer = blockIdx.x >> 5;
    int e0t = (blockIdx.x & 31)*128;
    const float* b1v = be1 + layer*HH;
    const float* b2v = be2 + layer*HH;

    {
        const uint4* s1 = (const uint4*)(g_wt + GWT_E1(layer));
        for (int i = t; i < 1024; i += 256){
            int n = i >> 3, kq = i & 7;
            *(uint4*)&smw[OFFG_W1 + n*GS + kq*4] = s1[i];
        }
        const uint4* s2 = (const uint4*)(g_wt + GWT_E2(layer));
        for (int i = t; i < 2048; i += 256){
            int n = i >> 4, kq = i & 15;
            *(uint4*)&smw[OFFG_W2 + n*GH + kq*4] = s2[i];
        }
    }
    for (int i = t; i < 4096; i += 256){
        int r = i >> 5, kw = i & 31;
        float d = (float)(e0t + r)*TABH;
        smw[OFFG_ES + r*GS + kw] = bf2(gsf(d, 2*kw), gsf(d, 2*kw+1));
    }
    __syncthreads();

    unsigned sb = (unsigned)__cvta_generic_to_shared(smw);
    int rowA = w*16 + (lane & 7) + ((lane >> 3) & 1)*8;
    int kSel = (lane >> 4)*4;
    unsigned aES = sb + (unsigned)(OFFG_ES + rowA*GS + kSel)*4u;
    unsigned aH  = sb + (unsigned)(OFFG_H  + rowA*GH + kSel)*4u;
    int rowB8 = lane & 7;
    int bSel  = (lane >> 3)*4;
    unsigned aW1 = sb + (unsigned)(OFFG_W1 + rowB8*GS + bSel)*4u;
    unsigned aW2 = sb + (unsigned)(OFFG_W2 + rowB8*GH + bSel)*4u;
    const unsigned S1STEP = 8u*GS*4u, S2STEP = 8u*GH*4u;
    int r0 = w*16 + g, r1 = r0 + 8;

    float d[16][4];
#pragma unroll
    for (int n = 0; n < 16; n++)
#pragma unroll
        for (int j = 0; j < 4; j++) d[n][j] = 0.f;

#pragma unroll
    for (int kt2 = 0; kt2 < 2; kt2++){
        unsigned a0,a1,a2,a3, a4,a5,a6,a7;
        ldsm4(aES + kt2*64u,       a0,a1,a2,a3);
        ldsm4(aES + kt2*64u + 32u, a4,a5,a6,a7);
#pragma unroll
        for (int ntl = 0; ntl < 16; ntl++){
            unsigned b0,b1,b2,b3;
            ldsm4(aW1 + ntl*S1STEP + kt2*64u, b0,b1,b2,b3);
            mma16(d[ntl], a0,a1,a2,a3, b0,b1);
            mma16(d[ntl], a4,a5,a6,a7, b2,b3);
        }
    }
#pragma unroll
    for (int ntl = 0; ntl < 16; ntl++){
        int c0 = ntl*8 + 2*tid;
        float b1a = b1v[c0], b1b = b1v[c0+1];
        smw[OFFG_H + r0*GH + (c0>>1)] = bf2(sspf(d[ntl][0]+b1a), sspf(d[ntl][1]+b1b));
        smw[OFFG_H + r1*GH + (c0>>1)] = bf2(sspf(d[ntl][2]+b1a), sspf(d[ntl][3]+b1b));
    }
    __syncthreads();

#pragma unroll
    for (int n = 0; n < 16; n++)
#pragma unroll
        for (int j = 0; j < 4; j++) d[n][j] = 0.f;
#pragma unroll
    for (int kt2 = 0; kt2 < 4; kt2++){
        unsigned a0,a1,a2,a3, a4,a5,a6,a7;
        ldsm4(aH + kt2*64u,       a0,a1,a2,a3);
        ldsm4(aH + kt2*64u + 32u, a4,a5,a6,a7);
#pragma unroll
        for (int ntl = 0; ntl < 16; ntl++){
            unsigned b0,b1,b2,b3;
            ldsm4(aW2 + ntl*S2STEP + kt2*64u, b0,b1,b2,b3);
            mma16(d[ntl], a0,a1,a2,a3, b0,b1);
            mma16(d[ntl], a4,a5,a6,a7, b2,b3);
        }
    }

    float dd0 = (float)(e0t + r0)*TABH, dd1 = (float)(e0t + r1)*TABH;
    float cut0 = 1.0f/(1.0f + __expf(5.0f*(dd0 - 3.5f)));
    float cut1 = 1.0f/(1.0f + __expf(5.0f*(dd1 - 3.5f)));
    float* tp0 = g_tab + ((size_t)layer*TABN + e0t + r0)*HH;
    float* tp1 = g_tab + ((size_t)layer*TABN + e0t + r1)*HH;
#pragma unroll
    for (int ntl = 0; ntl < 16; ntl++){
        int c0 = ntl*8 + 2*tid;
        float q0 = b2v[c0], q1 = b2v[c0+1];
        *(float2*)&tp0[c0] = make_float2((d[ntl][0]+q0)*cut0, (d[ntl][1]+q1)*cut0);
        *(float2*)&tp1[c0] = make_float2((d[ntl][2]+q0)*cut1, (d[ntl][3]+q1)*cut1);
    }
}

// ---------------------------------------------------------------------------
// node pre-GEMM (bf16 mma), SPLIT-N: 512 blocks; nhalf=0 -> S, nhalf=1 -> R
// ---------------------------------------------------------------------------
__global__ void __launch_bounds__(256, 4) k_pre(int layer){
    extern __shared__ unsigned smw[];
    int t = threadIdx.x, lane = t & 31, w = t >> 5;
    int g = lane >> 2, tid = lane & 3;
    int row0  = (blockIdx.x >> 1)*64;
    int nhalf = blockIdx.x & 1;

    {
        float4 z = make_float4(0.f,0.f,0.f,0.f);
        for (int i = t; i < 1024; i += 256){
            int r = i >> 4, c4 = i & 15;
            *(float4*)&g_msum[(row0 + r)*HH + nhalf*64 + c4*4] = z;
        }
    }
    for (int i = t; i < 64*64; i += 256){
        int r = i >> 6, kw = i & 63;
        float2 v = *(const float2*)&g_state[(row0 + r)*HH + 2*kw];
        smw[OFFP_A + r*NS + kw] = bf2(v.x, v.y);
    }
    {
        const uint4* src = (const uint4*)(g_wt + GWT_PRE(layer) + nhalf*128*64);
        for (int i = t; i < 2048; i += 256){
            int n = i >> 4, kq = i & 15;
            *(uint4*)&smw[OFFP_W + n*NS + kq*4] = src[i];
        }
    }
    __syncthreads();

    int wm = w & 3, wn = w >> 2;
    float d[8][4];
#pragma unroll
    for (int n = 0; n < 8; n++)
#pragma unroll
        for (int j = 0; j < 4; j++) d[n][j] = 0.f;

    unsigned sb = (unsigned)__cvta_generic_to_shared(smw);
    int rowA = wm*16 + (lane & 7) + ((lane >> 3) & 1)*8;
    int kSel = (lane >> 4)*4;
    unsigned aA = sb + (unsigned)(OFFP_A + rowA*NS + kSel)*4u;
    int rowBn = wn*64 + (lane & 7);
    int bSel  = (lane >> 3)*4;
    unsigned aW = sb + (unsigned)(OFFP_W + rowBn*NS + bSel)*4u;
    const unsigned NSTEP = 8u*NS*4u;

#pragma unroll
    for (int kt2 = 0; kt2 < 4; kt2++){
        unsigned a0,a1,a2,a3, a4,a5,a6,a7;
        ldsm4(aA + kt2*64u,       a0,a1,a2,a3);
        ldsm4(aA + kt2*64u + 32u, a4,a5,a6,a7);
#pragma unroll
        for (int ntl = 0; ntl < 8; ntl++){
            unsigned b0,b1,b2,b3;
            ldsm4(aW + ntl*NSTEP + kt2*64u, b0,b1,b2,b3);
            mma16(d[ntl], a0,a1,a2,a3, b0,b1);
            mma16(d[ntl], a4,a5,a6,a7, b2,b3);
        }
    }

    float* dst = nhalf ? g_R : g_S;
    int r0 = row0 + wm*16 + g, r1 = r0 + 8;
#pragma unroll
    for (int ntl = 0; ntl < 8; ntl++){
        int c = wn*64 + ntl*8 + 2*tid;
        *(float2*)&dst[r0*HH + c] = make_float2(d[ntl][0], d[ntl][1]);
        *(float2*)&dst[r1*HH + c] = make_float2(d[ntl][2], d[ntl][3]);
    }
}

// ---------------------------------------------------------------------------
// slim persistent edge kernel (R14 structure; gate pointers hoisted)
// ---------------------------------------------------------------------------
__global__ void __launch_bounds__(256, 3) k_edge(
    const int* __restrict__ atom_edges, const float* __restrict__ feats,
    const float* __restrict__ bn1, const float* __restrict__ bn2, int layer)
{
    extern __shared__ unsigned smw[];
    int t = threadIdx.x, lane = t & 31, w = t >> 5;
    int g = lane >> 2, tid = lane & 3;

    {
        const uint4* src = (const uint4*)(g_wt + GWT_N2(layer));
        for (int i = t; i < 2048; i += 256){
            int n = i >> 4, kq = i & 15;
            *(uint4*)&smw[OFFE_W2 + n*68 + kq*4] = src[i];
        }
    }

    int mt = w & 1, nq = w >> 1;
    int r0 = mt*16 + g, r1 = r0 + 8;
    int fc4 = (t & 31)*4;
    int fr8 = t >> 5;
    float4 b4 = *(const float4*)&bn1[fc4];
    float bn2h[4][2];
#pragma unroll
    for (int ntl = 0; ntl < 4; ntl++){
        int c0 = nq*32 + ntl*8 + 2*tid;
        bn2h[ntl][0] = bn2[c0]; bn2h[ntl][1] = bn2[c0+1];
    }

    unsigned sb = (unsigned)__cvta_generic_to_shared(smw);
    int rowA = mt*16 + (lane & 7) + ((lane >> 3) & 1)*8;
    int kSel = (lane >> 4)*4;
    unsigned aA1 = sb + (unsigned)(OFFE_A1 + rowA*68 + kSel)*4u;
    int rowBn = nq*32 + (lane & 7);
    int bSel  = (lane >> 3)*4;
    unsigned aW2 = sb + (unsigned)(OFFE_W2 + rowBn*68 + bSel)*4u;
    const unsigned NSTEP = 8u*68*4u;
    const float* T = g_tab + (size_t)layer*TABN*HH;

    for (int tile = blockIdx.x; tile < NTILES; tile += gridDim.x){
        int e0t = tile*MT;
        int off = g_off[tile >> 10];

        // gather LDGs + gate coords before barrier (reg targets; no smem hazard)
        float4 sv[4], rv[4];
#pragma unroll
        for (int j = 0; j < 4; j++){
            int e  = e0t + fr8 + 8*j;
            int sn = atom_edges[2*e]   + off;
            int rc = atom_edges[2*e+1] + off;
            sv[j] = *(const float4*)&g_S[sn*HH + fc4];
            rv[j] = *(const float4*)&g_R[rc*HH + fc4];
        }
        float u0 = feats[e0t + r0]*TABINV;
        float u1 = feats[e0t + r1]*TABINV;
        int i0 = (int)u0, i1 = (int)u1;
        float f0 = u0 - (float)i0, f1 = u1 - (float)i1;
        const float* pa = T + (size_t)i0*HH;
        const float* pb = T + (size_t)i1*HH;
        __syncthreads();   // prev tile's A1 reads complete

        // convert + store A1
#pragma unroll
        for (int j = 0; j < 4; j++){
            int m = fr8 + 8*j;
            unsigned w0 = bf2(sspf(sv[j].x + rv[j].x + b4.x), sspf(sv[j].y + rv[j].y + b4.y));
            unsigned w1 = bf2(sspf(sv[j].z + rv[j].z + b4.z), sspf(sv[j].w + rv[j].w + b4.w));
            *(uint2*)&smw[OFFE_A1 + m*68 + (fc4 >> 1)] = make_uint2(w0, w1);
        }

        // gate table prefetch (L2 hits, in flight through barrier into GEMM)
        float2 ga[4][2], gb[4][2];
#pragma unroll
        for (int ntl = 0; ntl < 4; ntl++){
            int c0 = nq*32 + ntl*8 + 2*tid;
            ga[ntl][0] = *(const float2*)&pa[c0];
            ga[ntl][1] = *(const float2*)&pa[HH + c0];
            gb[ntl][0] = *(const float2*)&pb[c0];
            gb[ntl][1] = *(const float2*)&pb[HH + c0];
        }
        __syncthreads();

        // GEMM: mn = A1 @ Wn2^T
        float dm[4][4];
#pragma unroll
        for (int i = 0; i < 4; i++)
#pragma unroll
            for (int j = 0; j < 4; j++) dm[i][j] = 0.0f;
#pragma unroll
        for (int kt2 = 0; kt2 < 4; kt2++){
            unsigned a0,a1,a2,a3, a4,a5,a6,a7;
            ldsm4(aA1 + kt2*64u,       a0,a1,a2,a3);
            ldsm4(aA1 + kt2*64u + 32u, a4,a5,a6,a7);
#pragma unroll
            for (int ntl = 0; ntl < 4; ntl++){
                unsigned b0,b1,b2,b3;
                ldsm4(aW2 + ntl*NSTEP + kt2*64u, b0,b1,b2,b3);
                mma16(dm[ntl], a0,a1,a2,a3, b0,b1);
                mma16(dm[ntl], a4,a5,a6,a7, b2,b3);
            }
        }

        // lerp gates + combine + vectorized reduction scatter
        int rcv0 = atom_edges[2*(e0t + r0) + 1] + off;
        int rcv1 = atom_edges[2*(e0t + r1) + 1] + off;
#pragma unroll
        for (int ntl = 0; ntl < 4; ntl++){
            int c0 = nq*32 + ntl*8 + 2*tid;
            float g0x = ga[ntl][0].x + (ga[ntl][1].x - ga[ntl][0].x)*f0;
            float g0y = ga[ntl][0].y + (ga[ntl][1].y - ga[ntl][0].y)*f0;
            float g1x = gb[ntl][0].x + (gb[ntl][1].x - gb[ntl][0].x)*f1;
            float g1y = gb[ntl][0].y + (gb[ntl][1].y - gb[ntl][0].y)*f1;
            red2(&g_msum[rcv0*HH + c0], (dm[ntl][0]+bn2h[ntl][0])*g0x,
                                        (dm[ntl][1]+bn2h[ntl][1])*g0y);
            red2(&g_msum[rcv1*HH + c0], (dm[ntl][2]+bn2h[ntl][0])*g1x,
                                        (dm[ntl][3]+bn2h[ntl][1])*g1y);
        }
    }
}

// ---------------------------------------------------------------------------
// node update (bf16 mma): state += ssp(msum @ Ws1 + bs1) @ Ws2 + bs2
// ---------------------------------------------------------------------------
__global__ void __launch_bounds__(256, 2) k_upd(int layer,
                      const float* __restrict__ bs1, const float* __restrict__ bs2,
                      float* __restrict__ out)
{
    extern __shared__ unsigned smw[];
    int t = threadIdx.x, lane = t & 31, w = t >> 5;
    int g = lane >> 2, tid = lane & 3;
    int row0 = blockIdx.x*64;

    for (int i = t; i < 64*64; i += 256){
        int r = i >> 6, kw = i & 63;
        float2 v = *(const float2*)&g_msum[(row0 + r)*HH + 2*kw];
        smw[OFFU_A + r*NS + kw] = bf2(v.x, v.y);
    }
    {
        const uint4* s1 = (const uint4*)(g_wt + GWT_S1(layer));
        const uint4* s2 = (const uint4*)(g_wt + GWT_S2(layer));
        for (int i = t; i < 2048; i += 256){
            int n = i >> 4, kq = i & 15;
            *(uint4*)&smw[OFFU_W1 + n*NS + kq*4] = s1[i];
            *(uint4*)&smw[OFFU_W2 + n*NS + kq*4] = s2[i];
        }
    }
    __syncthreads();

    int wm = w & 3, wn = w >> 2;
    unsigned sb = (unsigned)__cvta_generic_to_shared(smw);
    int rowA = wm*16 + (lane & 7) + ((lane >> 3) & 1)*8;
    int kSel = (lane >> 4)*4;
    unsigned aA  = sb + (unsigned)(OFFU_A + rowA*NS + kSel)*4u;
    unsigned aH  = sb + (unsigned)(OFFU_H + rowA*NS + kSel)*4u;
    int rowBn = wn*64 + (lane & 7);
    int bSel  = (lane >> 3)*4;
    unsigned aW1 = sb + (unsigned)(OFFU_W1 + rowBn*NS + bSel)*4u;
    unsigned aW2 = sb + (unsigned)(OFFU_W2 + rowBn*NS + bSel)*4u;
    const unsigned NSTEP = 8u*NS*4u;

    float d[8][4];
#pragma unroll
    for (int n = 0; n < 8; n++)
#pragma unroll
        for (int j = 0; j < 4; j++) d[n][j] = 0.f;
#pragma unroll
    for (int kt2 = 0; kt2 < 4; kt2++){
        unsigned a0,a1,a2,a3, a4,a5,a6,a7;
        ldsm4(aA + kt2*64u,       a0,a1,a2,a3);
        ldsm4(aA + kt2*64u + 32u, a4,a5,a6,a7);
#pragma unroll
        for (int ntl = 0; ntl < 8; ntl++){
            unsigned b0,b1,b2,b3;
            ldsm4(aW1 + ntl*NSTEP + kt2*64u, b0,b1,b2,b3);
            mma16(d[ntl], a0,a1,a2,a3, b0,b1);
            mma16(d[ntl], a4,a5,a6,a7, b2,b3);
        }
    }
    {
        int r0 = wm*16 + g, r1 = r0 + 8;
#pragma unroll
        for (int ntl = 0; ntl < 8; ntl++){
            int c0 = wn*64 + ntl*8 + 2*tid;
            float b1a = bs1[c0], b1b = bs1[c0+1];
            int cw = c0 >> 1;
            smw[OFFU_H + r0*NS + cw] = bf2(sspf(d[ntl][0]+b1a), sspf(d[ntl][1]+b1b));
            smw[OFFU_H + r1*NS + cw] = bf2(sspf(d[ntl][2]+b1a), sspf(d[ntl][3]+b1b));
        }
    }
    __syncthreads();

    float e2[8][4];
#pragma unroll
    for (int n = 0; n < 8; n++)
#pragma unroll
        for (int j = 0; j < 4; j++) e2[n][j] = 0.f;
#pragma unroll
    for (int kt2 = 0; kt2 < 4; kt2++){
        unsigned a0,a1,a2,a3, a4,a5,a6,a7;
        ldsm4(aH + kt2*64u,       a0,a1,a2,a3);
        ldsm4(aH + kt2*64u + 32u, a4,a5,a6,a7);
#pragma unroll
        for (int ntl = 0; ntl < 8; ntl++){
            unsigned b0,b1,b2,b3;
            ldsm4(aW2 + ntl*NSTEP + kt2*64u, b0,b1,b2,b3);
            mma16(e2[ntl], a0,a1,a2,a3, b0,b1);
            mma16(e2[ntl], a4,a5,a6,a7, b2,b3);
        }
    }
    {
        int r0 = row0 + wm*16 + g, r1 = r0 + 8;
#pragma unroll
        for (int ntl = 0; ntl < 8; ntl++){
            int c0 = wn*64 + ntl*8 + 2*tid;
            float b2a = bs2[c0], b2b = bs2[c0+1];
            float2 s0 = *(const float2*)&g_state[r0*HH + c0];
            float2 s1 = *(const float2*)&g_state[r1*HH + c0];
            float2 v0 = make_float2(s0.x + e2[ntl][0] + b2a, s0.y + e2[ntl][1] + b2b);
            float2 v1 = make_float2(s1.x + e2[ntl][2] + b2a, s1.y + e2[ntl][3] + b2b);
            *(float2*)&g_state[r0*HH + c0] = v0;
            *(float2*)&g_state[r1*HH + c0] = v1;
            *(float2*)&out[r0*HH + c0] = v0;
            *(float2*)&out[r1*HH + c0] = v1;
        }
    }
}

// ---------------------------------------------------------------------------
extern "C" void kernel_launch(void* const* d_in, const int* in_sizes, int n_in,
                              void* d_out, int out_size)
{
    const int*   nodes      = (const int*)  d_in[0];
    const int*   atom_edges = (const int*)  d_in[1];
    const float* feats      = (const float*)d_in[2];
    const int*   num_nodes  = (const int*)  d_in[3];
    // d_in[4] = num_atom_edges (all == EP, unused)
    const float* emb = (const float*)d_in[5];
    const float* Wn1 = (const float*)d_in[6];
    const float* bn1 = (const float*)d_in[7];
    const float* Wn2 = (const float*)d_in[8];
    const float* bn2 = (const float*)d_in[9];
    const float* We1 = (const float*)d_in[10];
    const float* be1 = (const float*)d_in[11];
    const float* We2 = (const float*)d_in[12];
    const float* be2 = (const float*)d_in[13];
    const float* Ws1 = (const float*)d_in[14];
    const float* bs1 = (const float*)d_in[15];
    const float* Ws2 = (const float*)d_in[16];
    const float* bs2 = (const float*)d_in[17];
    float* out = (float*)d_out;

    cudaFuncSetAttribute(k_edge, cudaFuncAttributeMaxDynamicSharedMemorySize,
                         SMEM_EDGE*sizeof(unsigned));
    cudaFuncSetAttribute(k_tab, cudaFuncAttributeMaxDynamicSharedMemorySize,
                         SMEM_GATE*sizeof(unsigned));
    cudaFuncSetAttribute(k_pre, cudaFuncAttributeMaxDynamicSharedMemorySize,
                         SMEM_PRE*sizeof(unsigned));
    cudaFuncSetAttribute(k_upd, cudaFuncAttributeMaxDynamicSharedMemorySize,
                         SMEM_UPD*sizeof(unsigned));

    k_setup<<<8192 + 624, 256>>>(nodes, emb, num_nodes, Wn1, Ws1, Ws2, Wn2, We1, We2);
    k_tab<<<NL*32, 256, SMEM_GATE*sizeof(unsigned)>>>(be1, be2);
    for (int l = 0; l < NL; l++){
        k_pre<<<NT/32, 256, SMEM_PRE*sizeof(unsigned)>>>(l);
        k_edge<<<GRID_EDGE, 256, SMEM_EDGE*sizeof(unsigned)>>>(atom_edges, feats,
            bn1 + l*HH, bn2 + l*HH, l);
        k_upd<<<NT/64, 256, SMEM_UPD*sizeof(unsigned)>>>(l, bs1 + l*HH, bs2 + l*HH,
                              out + (size_t)l*NT*HH);
    }
}